// round 4
// baseline (speedup 1.0000x reference)
#include <cuda_runtime.h>
#include <cuda_bf16.h>

#define DIM 100
#define NREL 1000
#define BATCH 8192
#define NITEMS (2 * BATCH)
#define N_ENT 500000
#define JOB_ITEMS 16
#define MAXJOBS 2048          // >= NREL + NITEMS/JOB_ITEMS = 2024
#define GITEMS 8

// ---- device scratch (zero-initialized at module load; g_count re-zeroed
//      at the end of every invocation by k_final) ----
__device__ float g_diff[NITEMS * DIM];
__device__ int   g_rel[NITEMS];
__device__ int   g_count[NREL];
__device__ int   g_items[NITEMS];
__device__ float g_score[NITEMS];
__device__ int   g_job_rel[MAXJOBS];
__device__ int   g_job_start[MAXJOBS];
__device__ int   g_job_len[MAXJOBS];
__device__ int   g_njobs;

__device__ __forceinline__ int clampi(int v, int lo, int hi) {
    return min(max(v, lo), hi);
}

// K1: one warp per item — diff = ent[h]-ent[t] into g_diff, record r, histogram.
__global__ __launch_bounds__(256)
void k_diff_hist(const int* __restrict__ pos, const int* __restrict__ neg,
                 const float* __restrict__ ent) {
    int item = (blockIdx.x * blockDim.x + threadIdx.x) >> 5;
    int lane = threadIdx.x & 31;
    if (item >= NITEMS) return;
    const int* trip = (item < BATCH) ? (pos + item * 3) : (neg + (item - BATCH) * 3);
    int h = clampi(trip[0], 0, N_ENT - 1);
    int r = clampi(trip[1], 0, NREL - 1);
    int t = clampi(trip[2], 0, N_ENT - 1);
    if (lane < 25) {
        const float4* hp = reinterpret_cast<const float4*>(ent + (long long)h * DIM);
        const float4* tp = reinterpret_cast<const float4*>(ent + (long long)t * DIM);
        float4 a = __ldg(hp + lane), b = __ldg(tp + lane);
        float4 d = make_float4(a.x - b.x, a.y - b.y, a.z - b.z, a.w - b.w);
        reinterpret_cast<float4*>(g_diff + (long long)item * DIM)[lane] = d;
    }
    if (lane == 0) {
        g_rel[item] = r;
        atomicAdd(&g_count[r], 1);
    }
}

// K2: single block: scan counts -> offsets, build job table (chunks of <=16),
// then scatter items into relation-sorted order using smem cursors.
__global__ __launch_bounds__(1024)
void k_scan_scatter() {
    __shared__ int s[1024];
    __shared__ int off[NREL];
    __shared__ int cur[NREL];
    int tid = threadIdx.x;

    // --- scan 1: item offsets ---
    int c = (tid < NREL) ? g_count[tid] : 0;
    s[tid] = c;
    __syncthreads();
    #pragma unroll
    for (int d = 1; d < 1024; d <<= 1) {
        int v = (tid >= d) ? s[tid - d] : 0;
        __syncthreads();
        s[tid] += v;
        __syncthreads();
    }
    int my_off = s[tid] - c;
    if (tid < NREL) { off[tid] = my_off; cur[tid] = my_off; }
    __syncthreads();

    // --- scan 2: job offsets (jobs of <= JOB_ITEMS items) ---
    int jc = (c + JOB_ITEMS - 1) / JOB_ITEMS;
    s[tid] = jc;
    __syncthreads();
    #pragma unroll
    for (int d = 1; d < 1024; d <<= 1) {
        int v = (tid >= d) ? s[tid - d] : 0;
        __syncthreads();
        s[tid] += v;
        __syncthreads();
    }
    int jbase = s[tid] - jc;
    if (tid < NREL) {
        for (int q = 0; q < jc; ++q) {
            g_job_rel[jbase + q]   = tid;
            g_job_start[jbase + q] = my_off + q * JOB_ITEMS;
            g_job_len[jbase + q]   = min(JOB_ITEMS, c - q * JOB_ITEMS);
        }
    }
    if (tid == 1023) g_njobs = s[1023];
    __syncthreads();

    // --- scatter (two-phase: batch loads, then smem atomics) ---
    int rs[NITEMS / 1024];
    #pragma unroll
    for (int b = 0; b < NITEMS / 1024; ++b)
        rs[b] = g_rel[tid + b * 1024];
    #pragma unroll
    for (int b = 0; b < NITEMS / 1024; ++b) {
        int slot = atomicAdd(&cur[rs[b]], 1);
        g_items[slot] = tid + b * 1024;
    }
}

// K3: one CTA per job. M transposed once into smem, reused for <=16 items.
#define MT_STRIDE 101
__global__ __launch_bounds__(128)
void k_gemm(const float* __restrict__ rel, const float* __restrict__ M) {
    __shared__ float Mt[DIM * MT_STRIDE];   // Mt[k*101+j] = M[j][k]
    __shared__ float ds[GITEMS][DIM];
    __shared__ float relrow[DIM];
    __shared__ int   itm[GITEMS];
    __shared__ float wred[4][GITEMS];

    int bid = blockIdx.x;
    if (bid >= g_njobs) return;
    int r    = g_job_rel[bid];
    int base = g_job_start[bid];
    int cnt  = g_job_len[bid];

    int tid  = threadIdx.x;
    int wid  = tid >> 5;
    int lane = tid & 31;

    if (tid < DIM) relrow[tid] = __ldg(&rel[r * DIM + tid]);
    const float* Mr = M + (long long)r * (DIM * DIM);
    for (int idx = tid; idx < DIM * DIM; idx += 128) {
        int row = idx / DIM, col = idx - row * DIM;
        Mt[col * MT_STRIDE + row] = __ldg(&Mr[idx]);
    }
    __syncthreads();

    for (int g = 0; g < cnt; g += GITEMS) {
        int nit = min(GITEMS, cnt - g);
        if (tid < GITEMS) itm[tid] = (tid < nit) ? g_items[base + g + tid] : 0;
        __syncthreads();
        for (int idx = tid; idx < GITEMS * DIM; idx += 128) {
            int it = idx / DIM, k = idx - it * DIM;
            ds[it][k] = (it < nit) ? g_diff[(long long)itm[it] * DIM + k] : 0.f;
        }
        __syncthreads();

        int j = tid;
        float acc[GITEMS];
        #pragma unroll
        for (int it = 0; it < GITEMS; ++it) acc[it] = (j < DIM) ? relrow[j] : 0.f;

        if (j < DIM) {
            #pragma unroll 5
            for (int k = 0; k < DIM; k += 4) {
                float m0 = Mt[(k + 0) * MT_STRIDE + j];
                float m1 = Mt[(k + 1) * MT_STRIDE + j];
                float m2 = Mt[(k + 2) * MT_STRIDE + j];
                float m3 = Mt[(k + 3) * MT_STRIDE + j];
                #pragma unroll
                for (int it = 0; it < GITEMS; ++it) {
                    float4 dv = *reinterpret_cast<const float4*>(&ds[it][k]);
                    acc[it] = fmaf(m0, dv.x, acc[it]);
                    acc[it] = fmaf(m1, dv.y, acc[it]);
                    acc[it] = fmaf(m2, dv.z, acc[it]);
                    acc[it] = fmaf(m3, dv.w, acc[it]);
                }
            }
        }

        #pragma unroll
        for (int it = 0; it < GITEMS; ++it) {
            float v = (j < DIM) ? fabsf(acc[it]) : 0.f;
            #pragma unroll
            for (int st = 16; st > 0; st >>= 1)
                v += __shfl_down_sync(0xffffffffu, v, st);
            if (lane == 0) wred[wid][it] = v;
        }
        __syncthreads();
        if (tid < nit)
            g_score[itm[tid]] = wred[0][tid] + wred[1][tid] + wred[2][tid] + wred[3][tid];
        __syncthreads();
    }
}

// K4: mean hinge (deterministic), then re-zero g_count for the next replay.
__global__ __launch_bounds__(256)
void k_final(float* __restrict__ out) {
    __shared__ float s[256];
    float a = 0.f;
    for (int i = threadIdx.x; i < BATCH; i += 256)
        a += fmaxf(0.f, g_score[i] - g_score[i + BATCH] + 1.0f);
    s[threadIdx.x] = a;
    __syncthreads();
    #pragma unroll
    for (int st = 128; st > 0; st >>= 1) {
        if (threadIdx.x < st) s[threadIdx.x] += s[threadIdx.x + st];
        __syncthreads();
    }
    if (threadIdx.x == 0) out[0] = s[0] / (float)BATCH;
    // prepare next invocation (graph replays the whole sequence)
    for (int i = threadIdx.x; i < NREL; i += 256) g_count[i] = 0;
}

extern "C" void kernel_launch(void* const* d_in, const int* in_sizes, int n_in,
                              void* d_out, int out_size) {
    const int*   pos = (const int*)d_in[0];
    const int*   neg = (const int*)d_in[1];
    const float* ent = (const float*)d_in[2];
    const float* rel = (const float*)d_in[3];
    const float* M   = (const float*)d_in[4];
    float* out = (float*)d_out;

    k_diff_hist<<<(NITEMS * 32 + 255) / 256, 256>>>(pos, neg, ent);
    k_scan_scatter<<<1, 1024>>>();
    k_gemm<<<MAXJOBS, 128>>>(rel, M);
    k_final<<<1, 256>>>(out);
}